// round 14
// baseline (speedup 1.0000x reference)
#include <cuda_runtime.h>
#include <math.h>

// Sinkhorn distance, B=4, P=2048, D=64, eps=0.1, max_iter=100, thresh=0.1
// Output layout: [cost(4) | pi(4*2048*2048) | C(4*2048*2048)]
// Per iteration: kU then kV, each 512 blocks x 512 threads at 4 blocks/SM
// (single wave). PDL + early launch_dependents overlaps node boundaries.
// Convergence freeze reproduced post-hoc from u snapshots (kErr/kSelect).

#define BB 4
#define PP 2048
#define DD 64
#define NROWS (BB*PP)                 // 8192
#define NEL ((size_t)BB*PP*PP)        // 16777216
#define S_CONST 14.426950408889634f   // (1/eps) * log2(e), eps = 0.1
#define EPSLN2  0.069314718055994531f // eps * ln2
#define NIT 100

__device__ float g_us[(NIT + 1) * NROWS];  // u snapshots (3.3MB)
__device__ float g_vs[(NIT + 1) * NROWS];  // v snapshots (3.3MB)
__device__ float g_errs[NIT];
__device__ int   g_selT;
__device__ float g_xn[NROWS];
__device__ float g_yn[NROWS];
__device__ float g_part[NROWS];

#define PDL_WAIT()    asm volatile("griddepcontrol.wait;" ::: "memory")
#define PDL_TRIGGER() asm volatile("griddepcontrol.launch_dependents;" ::: "memory")

__device__ __forceinline__ float ex2(float x) {
    float r;
    asm("ex2.approx.ftz.f32 %0, %1;" : "=f"(r) : "f"(x));
    return r;
}

// Exact online LSE step (log2 domain): keeps true running max.
__device__ __forceinline__ void olse(float& m, float& s, float a) {
    float e = ex2(0.0f - fabsf(m - a));
    s = (a > m) ? fmaf(s, e, 1.0f) : (s + e);
    m = fmaxf(m, a);
}

// Merge two (max,sum) log2-domain accumulators.
__device__ __forceinline__ void lse_merge(float& m, float& s, float m2, float s2) {
    float M = fmaxf(m, m2);
    s = fmaf(s, ex2(m - M), s2 * ex2(m2 - M));
    m = M;
}

__global__ void kInit() {
    int t = blockIdx.x * 256 + threadIdx.x;
    if (t < NROWS) { g_us[t] = 0.0f; g_vs[t] = 0.0f; }
}

// Row norms. One warp per row.
__global__ void kNorm(const float* __restrict__ x, const float* __restrict__ y) {
    PDL_WAIT();
    PDL_TRIGGER();
    int lane = threadIdx.x & 31;
    int gw = blockIdx.x * 8 + (threadIdx.x >> 5);
    const float* src = (gw < NROWS) ? x : y;
    float* dst = (gw < NROWS) ? g_xn : g_yn;
    int row = gw & (NROWS - 1);
    float2 v = ((const float2*)src)[row * 32 + lane];
    float s = fmaf(v.x, v.x, v.y * v.y);
    #pragma unroll
    for (int off = 16; off > 0; off >>= 1)
        s += __shfl_xor_sync(0xffffffffu, s, off);
    if (lane == 0) dst[row] = s;
}

// C[b,i,j] = ||x_i||^2 + ||y_j||^2 - 2 x_i . y_j
__global__ __launch_bounds__(256) void kC(const float* __restrict__ x,
                                          const float* __restrict__ y,
                                          float* __restrict__ Cout) {
    PDL_WAIT();
    PDL_TRIGGER();
    __shared__ float xs[64][68];
    __shared__ float ys[64][68];
    int b  = blockIdx.z;
    int i0 = blockIdx.y * 64;
    int j0 = blockIdx.x * 64;
    for (int idx = threadIdx.x; idx < 64 * 64; idx += 256) {
        int i = idx >> 6, d = idx & 63;
        xs[d][i] = x[((size_t)(b * PP + i0 + i)) * DD + d];
        ys[d][i] = y[((size_t)(b * PP + j0 + i)) * DD + d];
    }
    __syncthreads();
    int tx = threadIdx.x & 15, ty = threadIdx.x >> 4;
    float acc[4][4] = {};
    #pragma unroll 16
    for (int d = 0; d < 64; d++) {
        float4 xv = *(const float4*)&xs[d][ty * 4];
        float4 yv = *(const float4*)&ys[d][tx * 4];
        acc[0][0] = fmaf(xv.x, yv.x, acc[0][0]);
        acc[0][1] = fmaf(xv.x, yv.y, acc[0][1]);
        acc[0][2] = fmaf(xv.x, yv.z, acc[0][2]);
        acc[0][3] = fmaf(xv.x, yv.w, acc[0][3]);
        acc[1][0] = fmaf(xv.y, yv.x, acc[1][0]);
        acc[1][1] = fmaf(xv.y, yv.y, acc[1][1]);
        acc[1][2] = fmaf(xv.y, yv.z, acc[1][2]);
        acc[1][3] = fmaf(xv.y, yv.w, acc[1][3]);
        acc[2][0] = fmaf(xv.z, yv.x, acc[2][0]);
        acc[2][1] = fmaf(xv.z, yv.y, acc[2][1]);
        acc[2][2] = fmaf(xv.z, yv.z, acc[2][2]);
        acc[2][3] = fmaf(xv.z, yv.w, acc[2][3]);
        acc[3][0] = fmaf(xv.w, yv.x, acc[3][0]);
        acc[3][1] = fmaf(xv.w, yv.y, acc[3][1]);
        acc[3][2] = fmaf(xv.w, yv.z, acc[3][2]);
        acc[3][3] = fmaf(xv.w, yv.w, acc[3][3]);
    }
    int gi = b * PP + i0 + ty * 4;
    int gj = b * PP + j0 + tx * 4;
    float xn[4] = {g_xn[gi], g_xn[gi + 1], g_xn[gi + 2], g_xn[gi + 3]};
    float yn[4] = {g_yn[gj], g_yn[gj + 1], g_yn[gj + 2], g_yn[gj + 3]};
    #pragma unroll
    for (int r = 0; r < 4; r++) {
        float4 o;
        o.x = fmaf(-2.0f, acc[r][0], xn[r] + yn[0]);
        o.y = fmaf(-2.0f, acc[r][1], xn[r] + yn[1]);
        o.z = fmaf(-2.0f, acc[r][2], xn[r] + yn[2]);
        o.w = fmaf(-2.0f, acc[r][3], xn[r] + yn[3]);
        ((float4*)(Cout + ((size_t)(b * PP + i0 + ty * 4 + r)) * PP + j0))[tx] = o;
    }
}

// u half-step, all 4 batches: u(it+1) = eps*log_mu - eps*LSE_j((v(it)_j - C_ij)/eps)
// 512 blocks x 512 threads at 4 blocks/SM (single wave); 16 rows/block,
// 1 warp/row, 2 float2 olse chains per lane (low register pressure).
__global__ __launch_bounds__(512, 4) void kU(const float* __restrict__ C,
                                             int it, float eps_log_mu) {
    PDL_WAIT();
    PDL_TRIGGER();
    __shared__ __align__(16) float vs[PP];
    int tid = threadIdx.x;
    int b   = blockIdx.x >> 7;                 // 128 blocks per batch
    int i0  = (blockIdx.x & 127) * 16;         // first row in batch
    {
        const float4* vb = (const float4*)(g_vs + (size_t)it * NROWS + b * PP);
        float4 v = vb[tid];
        v.x *= S_CONST; v.y *= S_CONST; v.z *= S_CONST; v.w *= S_CONST;
        ((float4*)vs)[tid] = v;
    }
    __syncthreads();
    int w    = tid >> 5;                       // warp = row 0..15
    int lane = tid & 31;
    int row  = b * PP + i0 + w;
    const float2* Crow = (const float2*)(C + (size_t)row * PP);
    const float2* vs2  = (const float2*)vs;

    float m0 = -INFINITY, m1 = -INFINITY;
    float s0 = 0.0f, s1 = 0.0f;
    #pragma unroll 8
    for (int k = 0; k < 32; k++) {
        int idx = lane + k * 32;
        float2 c2 = __ldcg(Crow + idx);
        float2 v2 = vs2[idx];
        olse(m0, s0, fmaf(c2.x, -S_CONST, v2.x));
        olse(m1, s1, fmaf(c2.y, -S_CONST, v2.y));
    }
    lse_merge(m0, s0, m1, s1);
    #pragma unroll
    for (int off = 16; off > 0; off >>= 1) {
        float mo = __shfl_xor_sync(0xffffffffu, m0, off);
        float so = __shfl_xor_sync(0xffffffffu, s0, off);
        lse_merge(m0, s0, mo, so);
    }
    if (lane == 0) {
        float lse2 = m0 + __log2f(s0);
        g_us[(size_t)(it + 1) * NROWS + row] =
            fmaf(-EPSLN2, lse2, eps_log_mu);
    }
}

// v half-step, all 4 batches: v(it+1) = eps*log_nu - eps*LSE_i((u(it+1)_i - C_ij)/eps)
// 512 blocks x 512 threads at 4 blocks/SM (single wave); 16-col stripe x 2048
// rows per block. Warp w = rows [w*128, w*128+128); lane = (col, row-parity).
__global__ __launch_bounds__(512, 4) void kV(const float* __restrict__ C,
                                             int it, float eps_log_nu) {
    PDL_WAIT();
    PDL_TRIGGER();
    __shared__ __align__(16) float us[PP];
    __shared__ float pm[16][32];
    __shared__ float ps[16][32];
    int tid = threadIdx.x;
    int b   = blockIdx.x >> 7;                 // 128 stripes per batch
    int j0  = (blockIdx.x & 127) * 16;
    int w = tid >> 5, lane = tid & 31;

    {
        const float4* ub =
            (const float4*)(g_us + (size_t)(it + 1) * NROWS + b * PP);
        float4 u4 = ub[tid];
        u4.x *= S_CONST; u4.y *= S_CONST; u4.z *= S_CONST; u4.w *= S_CONST;
        ((float4*)us)[tid] = u4;
    }
    __syncthreads();
    int col = lane & 15;
    int rp  = lane >> 4;                       // row parity 0/1
    int r0  = w * 128;
    const float* p = C + (size_t)b * PP * PP + (size_t)(r0 + rp) * PP + j0 + col;
    const float* uA = us + r0 + rp;
    float m = -INFINITY, s = 0.0f;
    #pragma unroll 8
    for (int i = 0; i < 64; i++) {
        float c = __ldcg(p);
        p += 2 * PP;
        olse(m, s, fmaf(c, -S_CONST, uA[2 * i]));
    }
    pm[w][lane] = m;
    ps[w][lane] = s;
    __syncthreads();
    if (tid < 16) {
        float M = pm[0][tid], S = ps[0][tid];
        lse_merge(M, S, pm[0][tid + 16], ps[0][tid + 16]);
        #pragma unroll
        for (int k = 1; k < 16; k++) {
            lse_merge(M, S, pm[k][tid],      ps[k][tid]);
            lse_merge(M, S, pm[k][tid + 16], ps[k][tid + 16]);
        }
        float lse2 = M + __log2f(S);
        g_vs[(size_t)(it + 1) * NROWS + b * PP + j0 + tid] =
            fmaf(-EPSLN2, lse2, eps_log_nu);
    }
}

// err(t) = sum over all 8192 rows of |u(t+1)-u(t)|, one block per t.
__global__ __launch_bounds__(1024) void kErr() {
    PDL_WAIT();
    __shared__ float red[1024];
    int t = blockIdx.x;
    int tid = threadIdx.x;
    const float* u0 = g_us + (size_t)t * NROWS;
    const float* u1 = g_us + (size_t)(t + 1) * NROWS;
    float s = 0.0f;
    #pragma unroll
    for (int k = 0; k < NROWS / 1024; k++) {
        int i = tid + k * 1024;
        s += fabsf(u1[i] - u0[i]);
    }
    red[tid] = s;
    __syncthreads();
    for (int st = 512; st > 0; st >>= 1) {
        if (tid < st) red[tid] += red[tid + st];
        __syncthreads();
    }
    if (tid == 0) g_errs[t] = red[0];
}

// T = first t+1 with err(t) < thresh_tot, else 100 (reference freeze point).
__global__ void kSelect(float thresh_tot) {
    PDL_WAIT();
    int T = NIT;
    for (int t = 0; t < NIT; t++) {
        if (g_errs[t] < thresh_tot) { T = t + 1; break; }
    }
    g_selT = T;
}

// pi = exp2((u+v-C)*S) using snapshot T; per-row partial of sum(pi*C)
__global__ __launch_bounds__(256) void kFinal(const float* __restrict__ C,
                                              float* __restrict__ pi) {
    PDL_WAIT();
    __shared__ __align__(16) float wsm[PP];
    __shared__ float red[256];
    int row = blockIdx.x;
    int b = row >> 11;
    int T = g_selT;
    float ui = g_us[(size_t)T * NROWS + row];
    const float4* vb = (const float4*)(g_vs + (size_t)T * NROWS + b * PP);
    for (int t = threadIdx.x; t < PP / 4; t += 256) {
        float4 v4 = vb[t];
        v4.x = (ui + v4.x) * S_CONST;
        v4.y = (ui + v4.y) * S_CONST;
        v4.z = (ui + v4.z) * S_CONST;
        v4.w = (ui + v4.w) * S_CONST;
        ((float4*)wsm)[t] = v4;
    }
    __syncthreads();
    const float4* Crow = (const float4*)(C + (size_t)row * PP);
    float4* prow = (float4*)(pi + (size_t)row * PP);
    const float4* ws4 = (const float4*)wsm;
    float local = 0.0f;
    #pragma unroll
    for (int k = 0; k < 2; k++) {
        int idx = threadIdx.x + k * 256;
        float4 c4 = Crow[idx];
        float4 w4 = ws4[idx];
        float4 p4;
        p4.x = ex2(fmaf(c4.x, -S_CONST, w4.x));
        p4.y = ex2(fmaf(c4.y, -S_CONST, w4.y));
        p4.z = ex2(fmaf(c4.z, -S_CONST, w4.z));
        p4.w = ex2(fmaf(c4.w, -S_CONST, w4.w));
        prow[idx] = p4;
        local = fmaf(p4.x, c4.x, local);
        local = fmaf(p4.y, c4.y, local);
        local = fmaf(p4.z, c4.z, local);
        local = fmaf(p4.w, c4.w, local);
    }
    red[threadIdx.x] = local;
    __syncthreads();
    for (int st = 128; st > 0; st >>= 1) {
        if (threadIdx.x < st) red[threadIdx.x] += red[threadIdx.x + st];
        __syncthreads();
    }
    if (threadIdx.x == 0) g_part[row] = red[0];
}

__global__ void kCost(float* __restrict__ cost) {
    PDL_WAIT();
    __shared__ float red[256];
    int b = blockIdx.x;
    float t = 0.0f;
    #pragma unroll
    for (int k = 0; k < 8; k++)
        t += g_part[b * 2048 + threadIdx.x + k * 256];
    red[threadIdx.x] = t;
    __syncthreads();
    for (int st = 128; st > 0; st >>= 1) {
        if (threadIdx.x < st) red[threadIdx.x] += red[threadIdx.x + st];
        __syncthreads();
    }
    if (threadIdx.x == 0) cost[b] = red[0];
}

// Launch with programmatic stream serialization (PDL); fall back to plain.
static inline void pdl_launch(const void* fn, dim3 g, dim3 blk, void** args) {
    cudaLaunchConfig_t cfg = {};
    cfg.gridDim = g;
    cfg.blockDim = blk;
    cfg.dynamicSmemBytes = 0;
    cfg.stream = 0;
    cudaLaunchAttribute at[1];
    at[0].id = cudaLaunchAttributeProgrammaticStreamSerialization;
    at[0].val.programmaticStreamSerializationAllowed = 1;
    cfg.attrs = at;
    cfg.numAttrs = 1;
    if (cudaLaunchKernelExC(&cfg, fn, args) != cudaSuccess) {
        cudaLaunchKernel(fn, g, blk, args, 0, 0);
    }
}

extern "C" void kernel_launch(void* const* d_in, const int* in_sizes, int n_in,
                              void* d_out, int out_size) {
    const float* x = (const float*)d_in[0];
    const float* y = (const float*)d_in[1];
    float* out  = (float*)d_out;
    float* cost = out;                        // 4
    float* pi   = out + 4;                    // 16777216
    float* C    = out + 4 + (size_t)NEL;      // 16777216

    float log_mu = logf(1.0f / 2048.0f + 1e-8f);   // == log_nu (P1==P2)
    float eps_log_mu = 0.1f * log_mu;
    float thresh_tot = 0.1f * (float)BB;           // global-sum form of err<0.1

    kInit<<<(NROWS + 255) / 256, 256>>>();
    {
        void* args[] = { (void*)&x, (void*)&y };
        pdl_launch((const void*)kNorm, dim3(2 * NROWS / 8), dim3(256), args);
    }
    {
        void* args[] = { (void*)&x, (void*)&y, (void*)&C };
        pdl_launch((const void*)kC, dim3(PP / 64, PP / 64, BB), dim3(256), args);
    }
    for (int it = 0; it < NIT; it++) {
        int ii = it;
        {
            void* args[] = { (void*)&C, (void*)&ii, (void*)&eps_log_mu };
            pdl_launch((const void*)kU, dim3(512), dim3(512), args);
        }
        {
            void* args[] = { (void*)&C, (void*)&ii, (void*)&eps_log_mu };
            pdl_launch((const void*)kV, dim3(512), dim3(512), args);
        }
    }
    {
        void* args[] = {};
        pdl_launch((const void*)kErr, dim3(NIT), dim3(1024), args);
    }
    {
        void* args[] = { (void*)&thresh_tot };
        pdl_launch((const void*)kSelect, dim3(1), dim3(1), args);
    }
    {
        void* args[] = { (void*)&C, (void*)&pi };
        pdl_launch((const void*)kFinal, dim3(NROWS), dim3(256), args);
    }
    {
        void* args[] = { (void*)&cost };
        pdl_launch((const void*)kCost, dim3(BB), dim3(256), args);
    }
}

// round 15
// speedup vs baseline: 1.0114x; 1.0114x over previous
#include <cuda_runtime.h>
#include <math.h>

// Sinkhorn distance, B=4, P=2048, D=64, eps=0.1, max_iter=100, thresh=0.1
// Output layout: [cost(4) | pi(4*2048*2048) | C(4*2048*2048)]
// Best-known iteration kernels (R10 shapes: kU 1024x512 float4-olse,
// kV 256x512 2-chain) + post-hoc convergence (u/v snapshots, kErr/kSelect
// after the loop -> no per-iteration straggler) + PDL wait/trigger on all
// iterated nodes.

#define BB 4
#define PP 2048
#define DD 64
#define NROWS (BB*PP)                 // 8192
#define NEL ((size_t)BB*PP*PP)        // 16777216
#define S_CONST 14.426950408889634f   // (1/eps) * log2(e), eps = 0.1
#define EPSLN2  0.069314718055994531f // eps * ln2
#define NIT 100

__device__ float g_us[(NIT + 1) * NROWS];  // u snapshots (3.3MB)
__device__ float g_vs[(NIT + 1) * NROWS];  // v snapshots (3.3MB)
__device__ float g_errs[NIT];
__device__ int   g_selT;
__device__ float g_xn[NROWS];
__device__ float g_yn[NROWS];
__device__ float g_part[NROWS];

#define PDL_WAIT()    asm volatile("griddepcontrol.wait;" ::: "memory")
#define PDL_TRIGGER() asm volatile("griddepcontrol.launch_dependents;" ::: "memory")

__device__ __forceinline__ float ex2(float x) {
    float r;
    asm("ex2.approx.ftz.f32 %0, %1;" : "=f"(r) : "f"(x));
    return r;
}

// Exact online LSE step (log2 domain): keeps true running max.
__device__ __forceinline__ void olse(float& m, float& s, float a) {
    float e = ex2(0.0f - fabsf(m - a));
    s = (a > m) ? fmaf(s, e, 1.0f) : (s + e);
    m = fmaxf(m, a);
}

// Merge two (max,sum) log2-domain accumulators.
__device__ __forceinline__ void lse_merge(float& m, float& s, float m2, float s2) {
    float M = fmaxf(m, m2);
    s = fmaf(s, ex2(m - M), s2 * ex2(m2 - M));
    m = M;
}

__global__ void kInit() {
    int t = blockIdx.x * 256 + threadIdx.x;
    if (t < NROWS) { g_us[t] = 0.0f; g_vs[t] = 0.0f; }
}

// Row norms. One warp per row.
__global__ void kNorm(const float* __restrict__ x, const float* __restrict__ y) {
    PDL_WAIT();
    PDL_TRIGGER();
    int lane = threadIdx.x & 31;
    int gw = blockIdx.x * 8 + (threadIdx.x >> 5);
    const float* src = (gw < NROWS) ? x : y;
    float* dst = (gw < NROWS) ? g_xn : g_yn;
    int row = gw & (NROWS - 1);
    float2 v = ((const float2*)src)[row * 32 + lane];
    float s = fmaf(v.x, v.x, v.y * v.y);
    #pragma unroll
    for (int off = 16; off > 0; off >>= 1)
        s += __shfl_xor_sync(0xffffffffu, s, off);
    if (lane == 0) dst[row] = s;
}

// C[b,i,j] = ||x_i||^2 + ||y_j||^2 - 2 x_i . y_j
__global__ __launch_bounds__(256) void kC(const float* __restrict__ x,
                                          const float* __restrict__ y,
                                          float* __restrict__ Cout) {
    PDL_WAIT();
    PDL_TRIGGER();
    __shared__ float xs[64][68];
    __shared__ float ys[64][68];
    int b  = blockIdx.z;
    int i0 = blockIdx.y * 64;
    int j0 = blockIdx.x * 64;
    for (int idx = threadIdx.x; idx < 64 * 64; idx += 256) {
        int i = idx >> 6, d = idx & 63;
        xs[d][i] = x[((size_t)(b * PP + i0 + i)) * DD + d];
        ys[d][i] = y[((size_t)(b * PP + j0 + i)) * DD + d];
    }
    __syncthreads();
    int tx = threadIdx.x & 15, ty = threadIdx.x >> 4;
    float acc[4][4] = {};
    #pragma unroll 16
    for (int d = 0; d < 64; d++) {
        float4 xv = *(const float4*)&xs[d][ty * 4];
        float4 yv = *(const float4*)&ys[d][tx * 4];
        acc[0][0] = fmaf(xv.x, yv.x, acc[0][0]);
        acc[0][1] = fmaf(xv.x, yv.y, acc[0][1]);
        acc[0][2] = fmaf(xv.x, yv.z, acc[0][2]);
        acc[0][3] = fmaf(xv.x, yv.w, acc[0][3]);
        acc[1][0] = fmaf(xv.y, yv.x, acc[1][0]);
        acc[1][1] = fmaf(xv.y, yv.y, acc[1][1]);
        acc[1][2] = fmaf(xv.y, yv.z, acc[1][2]);
        acc[1][3] = fmaf(xv.y, yv.w, acc[1][3]);
        acc[2][0] = fmaf(xv.z, yv.x, acc[2][0]);
        acc[2][1] = fmaf(xv.z, yv.y, acc[2][1]);
        acc[2][2] = fmaf(xv.z, yv.z, acc[2][2]);
        acc[2][3] = fmaf(xv.z, yv.w, acc[2][3]);
        acc[3][0] = fmaf(xv.w, yv.x, acc[3][0]);
        acc[3][1] = fmaf(xv.w, yv.y, acc[3][1]);
        acc[3][2] = fmaf(xv.w, yv.z, acc[3][2]);
        acc[3][3] = fmaf(xv.w, yv.w, acc[3][3]);
    }
    int gi = b * PP + i0 + ty * 4;
    int gj = b * PP + j0 + tx * 4;
    float xn[4] = {g_xn[gi], g_xn[gi + 1], g_xn[gi + 2], g_xn[gi + 3]};
    float yn[4] = {g_yn[gj], g_yn[gj + 1], g_yn[gj + 2], g_yn[gj + 3]};
    #pragma unroll
    for (int r = 0; r < 4; r++) {
        float4 o;
        o.x = fmaf(-2.0f, acc[r][0], xn[r] + yn[0]);
        o.y = fmaf(-2.0f, acc[r][1], xn[r] + yn[1]);
        o.z = fmaf(-2.0f, acc[r][2], xn[r] + yn[2]);
        o.w = fmaf(-2.0f, acc[r][3], xn[r] + yn[3]);
        ((float4*)(Cout + ((size_t)(b * PP + i0 + ty * 4 + r)) * PP + j0))[tx] = o;
    }
}

// u half-step: u(it+1) = eps*log_mu - eps*LSE_j((v(it)_j - C_ij)/eps)
// 1024 blocks x 512 threads (3/SM); 8 rows/block, 64 threads/row,
// single-pass online LSE with 4 float4 chains per lane.
__global__ __launch_bounds__(512, 3) void kU(const float* __restrict__ C,
                                             int it, float eps_log_mu) {
    PDL_WAIT();
    PDL_TRIGGER();
    __shared__ __align__(16) float vs[PP];
    __shared__ float wm[16];
    __shared__ float ws[16];
    int tid = threadIdx.x;
    int b = blockIdx.x >> 8;                 // 256 blocks per batch
    const float4* vb = (const float4*)(g_vs + (size_t)it * NROWS + b * PP);
    for (int t = tid; t < PP / 4; t += 512) {
        float4 v = vb[t];
        v.x *= S_CONST; v.y *= S_CONST; v.z *= S_CONST; v.w *= S_CONST;
        ((float4*)vs)[t] = v;
    }
    __syncthreads();
    int w    = tid >> 5;
    int lane = tid & 31;
    int r    = tid >> 6;                     // row-in-block 0..7
    int t64  = tid & 63;
    int row  = blockIdx.x * 8 + r;
    const float4* Crow = (const float4*)(C + (size_t)row * PP);
    const float4* vs4  = (const float4*)vs;

    float m0 = -INFINITY, m1 = -INFINITY, m2 = -INFINITY, m3 = -INFINITY;
    float s0 = 0.0f, s1 = 0.0f, s2 = 0.0f, s3 = 0.0f;
    #pragma unroll
    for (int k = 0; k < 8; k++) {
        int idx = t64 + k * 64;
        float4 c4 = __ldcg(Crow + idx);
        float4 v4 = vs4[idx];
        olse(m0, s0, fmaf(c4.x, -S_CONST, v4.x));
        olse(m1, s1, fmaf(c4.y, -S_CONST, v4.y));
        olse(m2, s2, fmaf(c4.z, -S_CONST, v4.z));
        olse(m3, s3, fmaf(c4.w, -S_CONST, v4.w));
    }
    lse_merge(m0, s0, m1, s1);
    lse_merge(m2, s2, m3, s3);
    lse_merge(m0, s0, m2, s2);
    #pragma unroll
    for (int off = 16; off > 0; off >>= 1) {
        float mo = __shfl_xor_sync(0xffffffffu, m0, off);
        float so = __shfl_xor_sync(0xffffffffu, s0, off);
        lse_merge(m0, s0, mo, so);
    }
    if (lane == 0) { wm[w] = m0; ws[w] = s0; }
    __syncthreads();
    if (t64 == 0) {
        float M = wm[2 * r], S = ws[2 * r];
        lse_merge(M, S, wm[2 * r + 1], ws[2 * r + 1]);
        float lse2 = M + __log2f(S);
        g_us[(size_t)(it + 1) * NROWS + row] =
            fmaf(-EPSLN2, lse2, eps_log_mu);
    }
}

// v half-step: v(it+1) = eps*log_nu - eps*LSE_i((u(it+1)_i - C_ij)/eps)
// 256 blocks x 512 threads (3/SM); block = 32-col stripe x 2048 rows;
// warp w owns row group w*128, two 64-row chains per lane.
__global__ __launch_bounds__(512, 3) void kV(const float* __restrict__ C,
                                             int it, float eps_log_nu) {
    PDL_WAIT();
    PDL_TRIGGER();
    __shared__ __align__(16) float us[PP];
    __shared__ float pm[16][32];
    __shared__ float ps[16][32];
    int tid = threadIdx.x;
    int b  = blockIdx.x >> 6;                // 64 stripes per batch
    int j0 = (blockIdx.x & 63) * 32;
    int w = tid >> 5, lane = tid & 31;

    const float4* ub = (const float4*)(g_us + (size_t)(it + 1) * NROWS + b * PP);
    for (int t = tid; t < PP / 4; t += 512) {
        float4 u4 = ub[t];
        u4.x *= S_CONST; u4.y *= S_CONST; u4.z *= S_CONST; u4.w *= S_CONST;
        ((float4*)us)[t] = u4;
    }
    __syncthreads();
    int j  = j0 + lane;
    int r0 = w * 128;
    const float* pA = C + (size_t)b * PP * PP + (size_t)r0 * PP + j;
    const float* pB = pA + (size_t)64 * PP;
    const float* uA = us + r0;
    float mA = -INFINITY, sA = 0.0f, mB = -INFINITY, sB = 0.0f;
    #pragma unroll 8
    for (int rr = 0; rr < 64; rr++) {
        float cA = __ldcg(pA); pA += PP;
        float cB = __ldcg(pB); pB += PP;
        olse(mA, sA, fmaf(cA, -S_CONST, uA[rr]));
        olse(mB, sB, fmaf(cB, -S_CONST, uA[rr + 64]));
    }
    lse_merge(mA, sA, mB, sB);
    pm[w][lane] = mA;
    ps[w][lane] = sA;
    __syncthreads();
    if (tid < 32) {
        float M = pm[0][tid], S = ps[0][tid];
        #pragma unroll
        for (int k = 1; k < 16; k++)
            lse_merge(M, S, pm[k][tid], ps[k][tid]);
        float lse2 = M + __log2f(S);
        g_vs[(size_t)(it + 1) * NROWS + b * PP + j0 + tid] =
            fmaf(-EPSLN2, lse2, eps_log_nu);
    }
}

// err(t) = sum over all 8192 rows of |u(t+1)-u(t)|, one block per t.
__global__ __launch_bounds__(1024) void kErr() {
    PDL_WAIT();
    PDL_TRIGGER();
    __shared__ float red[1024];
    int t = blockIdx.x;
    int tid = threadIdx.x;
    const float* u0 = g_us + (size_t)t * NROWS;
    const float* u1 = g_us + (size_t)(t + 1) * NROWS;
    float s = 0.0f;
    #pragma unroll
    for (int k = 0; k < NROWS / 1024; k++) {
        int i = tid + k * 1024;
        s += fabsf(u1[i] - u0[i]);
    }
    red[tid] = s;
    __syncthreads();
    for (int st = 512; st > 0; st >>= 1) {
        if (tid < st) red[tid] += red[tid + st];
        __syncthreads();
    }
    if (tid == 0) g_errs[t] = red[0];
}

// T = first t+1 with err(t) < thresh_tot, else 100 (reference freeze point).
__global__ void kSelect(float thresh_tot) {
    PDL_WAIT();
    PDL_TRIGGER();
    int T = NIT;
    for (int t = 0; t < NIT; t++) {
        if (g_errs[t] < thresh_tot) { T = t + 1; break; }
    }
    g_selT = T;
}

// pi = exp2((u+v-C)*S) using snapshot T; per-row partial of sum(pi*C)
__global__ __launch_bounds__(256) void kFinal(const float* __restrict__ C,
                                              float* __restrict__ pi) {
    PDL_WAIT();
    PDL_TRIGGER();
    __shared__ __align__(16) float wsm[PP];
    __shared__ float red[256];
    int row = blockIdx.x;
    int b = row >> 11;
    int T = g_selT;
    float ui = g_us[(size_t)T * NROWS + row];
    const float4* vb = (const float4*)(g_vs + (size_t)T * NROWS + b * PP);
    for (int t = threadIdx.x; t < PP / 4; t += 256) {
        float4 v4 = vb[t];
        v4.x = (ui + v4.x) * S_CONST;
        v4.y = (ui + v4.y) * S_CONST;
        v4.z = (ui + v4.z) * S_CONST;
        v4.w = (ui + v4.w) * S_CONST;
        ((float4*)wsm)[t] = v4;
    }
    __syncthreads();
    const float4* Crow = (const float4*)(C + (size_t)row * PP);
    float4* prow = (float4*)(pi + (size_t)row * PP);
    const float4* ws4 = (const float4*)wsm;
    float local = 0.0f;
    #pragma unroll
    for (int k = 0; k < 2; k++) {
        int idx = threadIdx.x + k * 256;
        float4 c4 = Crow[idx];
        float4 w4 = ws4[idx];
        float4 p4;
        p4.x = ex2(fmaf(c4.x, -S_CONST, w4.x));
        p4.y = ex2(fmaf(c4.y, -S_CONST, w4.y));
        p4.z = ex2(fmaf(c4.z, -S_CONST, w4.z));
        p4.w = ex2(fmaf(c4.w, -S_CONST, w4.w));
        prow[idx] = p4;
        local = fmaf(p4.x, c4.x, local);
        local = fmaf(p4.y, c4.y, local);
        local = fmaf(p4.z, c4.z, local);
        local = fmaf(p4.w, c4.w, local);
    }
    red[threadIdx.x] = local;
    __syncthreads();
    for (int st = 128; st > 0; st >>= 1) {
        if (threadIdx.x < st) red[threadIdx.x] += red[threadIdx.x + st];
        __syncthreads();
    }
    if (threadIdx.x == 0) g_part[row] = red[0];
}

__global__ void kCost(float* __restrict__ cost) {
    PDL_WAIT();
    __shared__ float red[256];
    int b = blockIdx.x;
    float t = 0.0f;
    #pragma unroll
    for (int k = 0; k < 8; k++)
        t += g_part[b * 2048 + threadIdx.x + k * 256];
    red[threadIdx.x] = t;
    __syncthreads();
    for (int st = 128; st > 0; st >>= 1) {
        if (threadIdx.x < st) red[threadIdx.x] += red[threadIdx.x + st];
        __syncthreads();
    }
    if (threadIdx.x == 0) cost[b] = red[0];
}

// Launch with programmatic stream serialization (PDL); fall back to plain.
static inline void pdl_launch(const void* fn, dim3 g, dim3 blk, void** args) {
    cudaLaunchConfig_t cfg = {};
    cfg.gridDim = g;
    cfg.blockDim = blk;
    cfg.dynamicSmemBytes = 0;
    cfg.stream = 0;
    cudaLaunchAttribute at[1];
    at[0].id = cudaLaunchAttributeProgrammaticStreamSerialization;
    at[0].val.programmaticStreamSerializationAllowed = 1;
    cfg.attrs = at;
    cfg.numAttrs = 1;
    if (cudaLaunchKernelExC(&cfg, fn, args) != cudaSuccess) {
        cudaLaunchKernel(fn, g, blk, args, 0, 0);
    }
}

extern "C" void kernel_launch(void* const* d_in, const int* in_sizes, int n_in,
                              void* d_out, int out_size) {
    const float* x = (const float*)d_in[0];
    const float* y = (const float*)d_in[1];
    float* out  = (float*)d_out;
    float* cost = out;                        // 4
    float* pi   = out + 4;                    // 16777216
    float* C    = out + 4 + (size_t)NEL;      // 16777216

    float log_mu = logf(1.0f / 2048.0f + 1e-8f);   // == log_nu (P1==P2)
    float eps_log_mu = 0.1f * log_mu;
    float thresh_tot = 0.1f * (float)BB;           // global-sum form of err<0.1

    kInit<<<(NROWS + 255) / 256, 256>>>();
    {
        void* args[] = { (void*)&x, (void*)&y };
        pdl_launch((const void*)kNorm, dim3(2 * NROWS / 8), dim3(256), args);
    }
    {
        void* args[] = { (void*)&x, (void*)&y, (void*)&C };
        pdl_launch((const void*)kC, dim3(PP / 64, PP / 64, BB), dim3(256), args);
    }
    for (int it = 0; it < NIT; it++) {
        int ii = it;
        {
            void* args[] = { (void*)&C, (void*)&ii, (void*)&eps_log_mu };
            pdl_launch((const void*)kU, dim3(NROWS / 8), dim3(512), args);
        }
        {
            void* args[] = { (void*)&C, (void*)&ii, (void*)&eps_log_mu };
            pdl_launch((const void*)kV, dim3(BB * (PP / 32)), dim3(512), args);
        }
    }
    {
        void* args[] = {};
        pdl_launch((const void*)kErr, dim3(NIT), dim3(1024), args);
    }
    {
        void* args[] = { (void*)&thresh_tot };
        pdl_launch((const void*)kSelect, dim3(1), dim3(1), args);
    }
    {
        void* args[] = { (void*)&C, (void*)&pi };
        pdl_launch((const void*)kFinal, dim3(NROWS), dim3(256), args);
    }
    {
        void* args[] = { (void*)&cost };
        pdl_launch((const void*)kCost, dim3(BB), dim3(256), args);
    }
}

// round 16
// speedup vs baseline: 1.2210x; 1.2071x over previous
#include <cuda_runtime.h>
#include <math.h>

// Sinkhorn distance, B=4, P=2048, D=64, eps=0.1, max_iter=100, thresh=0.1
// Output layout: [cost(4) | pi(4*2048*2048) | C(4*2048*2048)]
// R10 iteration-kernel shapes (best measured), trigger-free PDL (race-free),
// per-iteration done-flag replaced by u/v snapshots + post-hoc kErr/kSelect.

#define BB 4
#define PP 2048
#define DD 64
#define NROWS (BB*PP)                 // 8192
#define NEL ((size_t)BB*PP*PP)        // 16777216
#define S_CONST 14.426950408889634f   // (1/eps) * log2(e), eps = 0.1
#define EPSLN2  0.069314718055994531f // eps * ln2
#define NIT 100

__device__ float g_us[(NIT + 1) * NROWS];  // u snapshots (3.3MB)
__device__ float g_vs[(NIT + 1) * NROWS];  // v snapshots (3.3MB)
__device__ float g_errs[NIT];
__device__ int   g_selT;
__device__ float g_xn[NROWS];
__device__ float g_yn[NROWS];
__device__ float g_part[NROWS];

#define PDL_WAIT() asm volatile("griddepcontrol.wait;" ::: "memory")

__device__ __forceinline__ float ex2(float x) {
    float r;
    asm("ex2.approx.ftz.f32 %0, %1;" : "=f"(r) : "f"(x));
    return r;
}

// Exact online LSE step (log2 domain): keeps true running max.
__device__ __forceinline__ void olse(float& m, float& s, float a) {
    float e = ex2(0.0f - fabsf(m - a));
    s = (a > m) ? fmaf(s, e, 1.0f) : (s + e);
    m = fmaxf(m, a);
}

// Merge two (max,sum) log2-domain accumulators.
__device__ __forceinline__ void lse_merge(float& m, float& s, float m2, float s2) {
    float M = fmaxf(m, m2);
    s = fmaf(s, ex2(m - M), s2 * ex2(m2 - M));
    m = M;
}

__global__ void kInit() {
    int t = blockIdx.x * 256 + threadIdx.x;
    if (t < NROWS) { g_us[t] = 0.0f; g_vs[t] = 0.0f; }
}

// Row norms. One warp per row.
__global__ void kNorm(const float* __restrict__ x, const float* __restrict__ y) {
    PDL_WAIT();
    int lane = threadIdx.x & 31;
    int gw = blockIdx.x * 8 + (threadIdx.x >> 5);
    const float* src = (gw < NROWS) ? x : y;
    float* dst = (gw < NROWS) ? g_xn : g_yn;
    int row = gw & (NROWS - 1);
    float2 v = ((const float2*)src)[row * 32 + lane];
    float s = fmaf(v.x, v.x, v.y * v.y);
    #pragma unroll
    for (int off = 16; off > 0; off >>= 1)
        s += __shfl_xor_sync(0xffffffffu, s, off);
    if (lane == 0) dst[row] = s;
}

// C[b,i,j] = ||x_i||^2 + ||y_j||^2 - 2 x_i . y_j
__global__ __launch_bounds__(256) void kC(const float* __restrict__ x,
                                          const float* __restrict__ y,
                                          float* __restrict__ Cout) {
    PDL_WAIT();
    __shared__ float xs[64][68];
    __shared__ float ys[64][68];
    int b  = blockIdx.z;
    int i0 = blockIdx.y * 64;
    int j0 = blockIdx.x * 64;
    for (int idx = threadIdx.x; idx < 64 * 64; idx += 256) {
        int i = idx >> 6, d = idx & 63;
        xs[d][i] = x[((size_t)(b * PP + i0 + i)) * DD + d];
        ys[d][i] = y[((size_t)(b * PP + j0 + i)) * DD + d];
    }
    __syncthreads();
    int tx = threadIdx.x & 15, ty = threadIdx.x >> 4;
    float acc[4][4] = {};
    #pragma unroll 16
    for (int d = 0; d < 64; d++) {
        float4 xv = *(const float4*)&xs[d][ty * 4];
        float4 yv = *(const float4*)&ys[d][tx * 4];
        acc[0][0] = fmaf(xv.x, yv.x, acc[0][0]);
        acc[0][1] = fmaf(xv.x, yv.y, acc[0][1]);
        acc[0][2] = fmaf(xv.x, yv.z, acc[0][2]);
        acc[0][3] = fmaf(xv.x, yv.w, acc[0][3]);
        acc[1][0] = fmaf(xv.y, yv.x, acc[1][0]);
        acc[1][1] = fmaf(xv.y, yv.y, acc[1][1]);
        acc[1][2] = fmaf(xv.y, yv.z, acc[1][2]);
        acc[1][3] = fmaf(xv.y, yv.w, acc[1][3]);
        acc[2][0] = fmaf(xv.z, yv.x, acc[2][0]);
        acc[2][1] = fmaf(xv.z, yv.y, acc[2][1]);
        acc[2][2] = fmaf(xv.z, yv.z, acc[2][2]);
        acc[2][3] = fmaf(xv.z, yv.w, acc[2][3]);
        acc[3][0] = fmaf(xv.w, yv.x, acc[3][0]);
        acc[3][1] = fmaf(xv.w, yv.y, acc[3][1]);
        acc[3][2] = fmaf(xv.w, yv.z, acc[3][2]);
        acc[3][3] = fmaf(xv.w, yv.w, acc[3][3]);
    }
    int gi = b * PP + i0 + ty * 4;
    int gj = b * PP + j0 + tx * 4;
    float xn[4] = {g_xn[gi], g_xn[gi + 1], g_xn[gi + 2], g_xn[gi + 3]};
    float yn[4] = {g_yn[gj], g_yn[gj + 1], g_yn[gj + 2], g_yn[gj + 3]};
    #pragma unroll
    for (int r = 0; r < 4; r++) {
        float4 o;
        o.x = fmaf(-2.0f, acc[r][0], xn[r] + yn[0]);
        o.y = fmaf(-2.0f, acc[r][1], xn[r] + yn[1]);
        o.z = fmaf(-2.0f, acc[r][2], xn[r] + yn[2]);
        o.w = fmaf(-2.0f, acc[r][3], xn[r] + yn[3]);
        ((float4*)(Cout + ((size_t)(b * PP + i0 + ty * 4 + r)) * PP + j0))[tx] = o;
    }
}

// u half-step: u(it+1) = eps*log_mu - eps*LSE_j((v(it)_j - C_ij)/eps)
// 1024 blocks x 512 threads (3/SM); 8 rows/block, 64 threads/row,
// single-pass online LSE with 4 float4 chains per lane.  (R10 shape)
__global__ __launch_bounds__(512, 3) void kU(const float* __restrict__ C,
                                             int it, float eps_log_mu) {
    PDL_WAIT();
    __shared__ __align__(16) float vs[PP];
    __shared__ float wm[16];
    __shared__ float ws[16];
    int tid = threadIdx.x;
    int b = blockIdx.x >> 8;                 // 256 blocks per batch
    const float4* vb = (const float4*)(g_vs + (size_t)it * NROWS + b * PP);
    for (int t = tid; t < PP / 4; t += 512) {
        float4 v = vb[t];
        v.x *= S_CONST; v.y *= S_CONST; v.z *= S_CONST; v.w *= S_CONST;
        ((float4*)vs)[t] = v;
    }
    __syncthreads();
    int w    = tid >> 5;
    int lane = tid & 31;
    int r    = tid >> 6;                     // row-in-block 0..7
    int t64  = tid & 63;
    int row  = blockIdx.x * 8 + r;
    const float4* Crow = (const float4*)(C + (size_t)row * PP);
    const float4* vs4  = (const float4*)vs;

    float m0 = -INFINITY, m1 = -INFINITY, m2 = -INFINITY, m3 = -INFINITY;
    float s0 = 0.0f, s1 = 0.0f, s2 = 0.0f, s3 = 0.0f;
    #pragma unroll
    for (int k = 0; k < 8; k++) {
        int idx = t64 + k * 64;
        float4 c4 = __ldcg(Crow + idx);
        float4 v4 = vs4[idx];
        olse(m0, s0, fmaf(c4.x, -S_CONST, v4.x));
        olse(m1, s1, fmaf(c4.y, -S_CONST, v4.y));
        olse(m2, s2, fmaf(c4.z, -S_CONST, v4.z));
        olse(m3, s3, fmaf(c4.w, -S_CONST, v4.w));
    }
    lse_merge(m0, s0, m1, s1);
    lse_merge(m2, s2, m3, s3);
    lse_merge(m0, s0, m2, s2);
    #pragma unroll
    for (int off = 16; off > 0; off >>= 1) {
        float mo = __shfl_xor_sync(0xffffffffu, m0, off);
        float so = __shfl_xor_sync(0xffffffffu, s0, off);
        lse_merge(m0, s0, mo, so);
    }
    if (lane == 0) { wm[w] = m0; ws[w] = s0; }
    __syncthreads();
    if (t64 == 0) {
        float M = wm[2 * r], S = ws[2 * r];
        lse_merge(M, S, wm[2 * r + 1], ws[2 * r + 1]);
        float lse2 = M + __log2f(S);
        g_us[(size_t)(it + 1) * NROWS + row] =
            fmaf(-EPSLN2, lse2, eps_log_mu);
    }
}

// v half-step: v(it+1) = eps*log_nu - eps*LSE_i((u(it+1)_i - C_ij)/eps)
// 256 blocks x 512 threads (3/SM); block = 32-col stripe x 2048 rows;
// warp w owns row group w*128, two 64-row chains per lane.  (R10 shape)
__global__ __launch_bounds__(512, 3) void kV(const float* __restrict__ C,
                                             int it, float eps_log_nu) {
    PDL_WAIT();
    __shared__ __align__(16) float us[PP];
    __shared__ float pm[16][32];
    __shared__ float ps[16][32];
    int tid = threadIdx.x;
    int b  = blockIdx.x >> 6;                // 64 stripes per batch
    int j0 = (blockIdx.x & 63) * 32;
    int w = tid >> 5, lane = tid & 31;

    const float4* ub = (const float4*)(g_us + (size_t)(it + 1) * NROWS + b * PP);
    for (int t = tid; t < PP / 4; t += 512) {
        float4 u4 = ub[t];
        u4.x *= S_CONST; u4.y *= S_CONST; u4.z *= S_CONST; u4.w *= S_CONST;
        ((float4*)us)[t] = u4;
    }
    __syncthreads();
    int j  = j0 + lane;
    int r0 = w * 128;
    const float* pA = C + (size_t)b * PP * PP + (size_t)r0 * PP + j;
    const float* pB = pA + (size_t)64 * PP;
    const float* uA = us + r0;
    float mA = -INFINITY, sA = 0.0f, mB = -INFINITY, sB = 0.0f;
    #pragma unroll 8
    for (int rr = 0; rr < 64; rr++) {
        float cA = __ldcg(pA); pA += PP;
        float cB = __ldcg(pB); pB += PP;
        olse(mA, sA, fmaf(cA, -S_CONST, uA[rr]));
        olse(mB, sB, fmaf(cB, -S_CONST, uA[rr + 64]));
    }
    lse_merge(mA, sA, mB, sB);
    pm[w][lane] = mA;
    ps[w][lane] = sA;
    __syncthreads();
    if (tid < 32) {
        float M = pm[0][tid], S = ps[0][tid];
        #pragma unroll
        for (int k = 1; k < 16; k++)
            lse_merge(M, S, pm[k][tid], ps[k][tid]);
        float lse2 = M + __log2f(S);
        g_vs[(size_t)(it + 1) * NROWS + b * PP + j0 + tid] =
            fmaf(-EPSLN2, lse2, eps_log_nu);
    }
}

// err(t) = sum over all 8192 rows of |u(t+1)-u(t)|, one block per t.
__global__ __launch_bounds__(1024) void kErr() {
    PDL_WAIT();
    __shared__ float red[1024];
    int t = blockIdx.x;
    int tid = threadIdx.x;
    const float* u0 = g_us + (size_t)t * NROWS;
    const float* u1 = g_us + (size_t)(t + 1) * NROWS;
    float s = 0.0f;
    #pragma unroll
    for (int k = 0; k < NROWS / 1024; k++) {
        int i = tid + k * 1024;
        s += fabsf(u1[i] - u0[i]);
    }
    red[tid] = s;
    __syncthreads();
    for (int st = 512; st > 0; st >>= 1) {
        if (tid < st) red[tid] += red[tid + st];
        __syncthreads();
    }
    if (tid == 0) g_errs[t] = red[0];
}

// T = first t+1 with err(t) < thresh_tot, else 100 (reference freeze point).
__global__ void kSelect(float thresh_tot) {
    PDL_WAIT();
    int T = NIT;
    for (int t = 0; t < NIT; t++) {
        if (g_errs[t] < thresh_tot) { T = t + 1; break; }
    }
    g_selT = T;
}

// pi = exp2((u+v-C)*S) using snapshot T; per-row partial of sum(pi*C)
__global__ __launch_bounds__(256) void kFinal(const float* __restrict__ C,
                                              float* __restrict__ pi) {
    PDL_WAIT();
    __shared__ __align__(16) float wsm[PP];
    __shared__ float red[256];
    int row = blockIdx.x;
    int b = row >> 11;
    int T = g_selT;
    float ui = g_us[(size_t)T * NROWS + row];
    const float4* vb = (const float4*)(g_vs + (size_t)T * NROWS + b * PP);
    for (int t = threadIdx.x; t < PP / 4; t += 256) {
        float4 v4 = vb[t];
        v4.x = (ui + v4.x) * S_CONST;
        v4.y = (ui + v4.y) * S_CONST;
        v4.z = (ui + v4.z) * S_CONST;
        v4.w = (ui + v4.w) * S_CONST;
        ((float4*)wsm)[t] = v4;
    }
    __syncthreads();
    const float4* Crow = (const float4*)(C + (size_t)row * PP);
    float4* prow = (float4*)(pi + (size_t)row * PP);
    const float4* ws4 = (const float4*)wsm;
    float local = 0.0f;
    #pragma unroll
    for (int k = 0; k < 2; k++) {
        int idx = threadIdx.x + k * 256;
        float4 c4 = Crow[idx];
        float4 w4 = ws4[idx];
        float4 p4;
        p4.x = ex2(fmaf(c4.x, -S_CONST, w4.x));
        p4.y = ex2(fmaf(c4.y, -S_CONST, w4.y));
        p4.z = ex2(fmaf(c4.z, -S_CONST, w4.z));
        p4.w = ex2(fmaf(c4.w, -S_CONST, w4.w));
        prow[idx] = p4;
        local = fmaf(p4.x, c4.x, local);
        local = fmaf(p4.y, c4.y, local);
        local = fmaf(p4.z, c4.z, local);
        local = fmaf(p4.w, c4.w, local);
    }
    red[threadIdx.x] = local;
    __syncthreads();
    for (int st = 128; st > 0; st >>= 1) {
        if (threadIdx.x < st) red[threadIdx.x] += red[threadIdx.x + st];
        __syncthreads();
    }
    if (threadIdx.x == 0) g_part[row] = red[0];
}

__global__ void kCost(float* __restrict__ cost) {
    PDL_WAIT();
    __shared__ float red[256];
    int b = blockIdx.x;
    float t = 0.0f;
    #pragma unroll
    for (int k = 0; k < 8; k++)
        t += g_part[b * 2048 + threadIdx.x + k * 256];
    red[threadIdx.x] = t;
    __syncthreads();
    for (int st = 128; st > 0; st >>= 1) {
        if (threadIdx.x < st) red[threadIdx.x] += red[threadIdx.x + st];
        __syncthreads();
    }
    if (threadIdx.x == 0) cost[b] = red[0];
}

// Launch with programmatic stream serialization (PDL, no explicit trigger);
// fall back to plain launch on synchronous error.
static inline void pdl_launch(const void* fn, dim3 g, dim3 blk, void** args) {
    cudaLaunchConfig_t cfg = {};
    cfg.gridDim = g;
    cfg.blockDim = blk;
    cfg.dynamicSmemBytes = 0;
    cfg.stream = 0;
    cudaLaunchAttribute at[1];
    at[0].id = cudaLaunchAttributeProgrammaticStreamSerialization;
    at[0].val.programmaticStreamSerializationAllowed = 1;
    cfg.attrs = at;
    cfg.numAttrs = 1;
    if (cudaLaunchKernelExC(&cfg, fn, args) != cudaSuccess) {
        cudaLaunchKernel(fn, g, blk, args, 0, 0);
    }
}

extern "C" void kernel_launch(void* const* d_in, const int* in_sizes, int n_in,
                              void* d_out, int out_size) {
    const float* x = (const float*)d_in[0];
    const float* y = (const float*)d_in[1];
    float* out  = (float*)d_out;
    float* cost = out;                        // 4
    float* pi   = out + 4;                    // 16777216
    float* C    = out + 4 + (size_t)NEL;      // 16777216

    float log_mu = logf(1.0f / 2048.0f + 1e-8f);   // == log_nu (P1==P2)
    float eps_log_mu = 0.1f * log_mu;
    float thresh_tot = 0.1f * (float)BB;           // global-sum form of err<0.1

    kInit<<<(NROWS + 255) / 256, 256>>>();
    {
        void* args[] = { (void*)&x, (void*)&y };
        pdl_launch((const void*)kNorm, dim3(2 * NROWS / 8), dim3(256), args);
    }
    {
        void* args[] = { (void*)&x, (void*)&y, (void*)&C };
        pdl_launch((const void*)kC, dim3(PP / 64, PP / 64, BB), dim3(256), args);
    }
    for (int it = 0; it < NIT; it++) {
        int ii = it;
        {
            void* args[] = { (void*)&C, (void*)&ii, (void*)&eps_log_mu };
            pdl_launch((const void*)kU, dim3(NROWS / 8), dim3(512), args);
        }
        {
            void* args[] = { (void*)&C, (void*)&ii, (void*)&eps_log_mu };
            pdl_launch((const void*)kV, dim3(BB * (PP / 32)), dim3(512), args);
        }
    }
    {
        void* args[] = {};
        pdl_launch((const void*)kErr, dim3(NIT), dim3(1024), args);
    }
    {
        void* args[] = { (void*)&thresh_tot };
        pdl_launch((const void*)kSelect, dim3(1), dim3(1), args);
    }
    {
        void* args[] = { (void*)&C, (void*)&pi };
        pdl_launch((const void*)kFinal, dim3(NROWS), dim3(256), args);
    }
    {
        void* args[] = { (void*)&cost };
        pdl_launch((const void*)kCost, dim3(BB), dim3(256), args);
    }
}